// round 1
// baseline (speedup 1.0000x reference)
#include <cuda_runtime.h>
#include <cstdint>

#define NN 8192
#define NW 128            // NN/64 words per mask row
#define THR 0.7f
#define IOU_THR 0.5f
#define EPSF 1e-9f
#define SCALER_F 2.740625f   // 3508/1280

// ---------------- scratch (device globals; no allocation allowed) ----------
__device__ unsigned long long g_keys[NN];
__device__ int g_V;
__device__ float4 g_box[NN];
__device__ float2 g_conf[NN];
__device__ float  g_area[NN];
__device__ unsigned long long g_mask[(size_t)NN * NW];   // 8 MB
__device__ unsigned long long g_keep[NW];

// ---------------- kernel 1: build sort keys --------------------------------
__global__ void build_keys_kernel(const float* __restrict__ conf) {
    int i = blockIdx.x * blockDim.x + threadIdx.x;
    if (i >= NN) return;
    float c0 = conf[2 * i], c1 = conf[2 * i + 1];
    bool valid = (c0 > THR) || (c1 > THR);
    float s = fmaxf(c0, c1);
    float ms = valid ? s : -__int_as_float(0x7f800000);   // -inf
    unsigned int b = __float_as_uint(ms);
    b = (b & 0x80000000u) ? ~b : (b | 0x80000000u);       // monotonic map
    g_keys[i] = ((unsigned long long)b << 32) | (unsigned int)(~i);
}

// ---------------- kernel 2: single-block bitonic sort + count + gather -----
__global__ __launch_bounds__(1024, 1)
void sort_kernel(const float* __restrict__ bboxes, const float* __restrict__ conf) {
    extern __shared__ unsigned long long sk[];   // 8192 * 8 = 64 KB
    int tid = threadIdx.x;

    for (int i = tid; i < NN; i += 1024) sk[i] = g_keys[i];
    __syncthreads();

    // descending bitonic sort (stable via ~i in low bits)
    for (int k = 2; k <= NN; k <<= 1) {
        for (int j = k >> 1; j > 0; j >>= 1) {
            for (int i = tid; i < NN; i += 1024) {
                int l = i ^ j;
                if (l > i) {
                    unsigned long long a = sk[i], b = sk[l];
                    bool desc = ((i & k) == 0);
                    if ((a < b) == desc) { sk[i] = b; sk[l] = a; }
                }
            }
            __syncthreads();
        }
    }

    // count valid (top bit of mapped score set <=> finite positive score)
    __shared__ int cnt;
    if (tid == 0) cnt = 0;
    __syncthreads();
    int local = 0;
    for (int i = tid; i < NN; i += 1024)
        if (sk[i] >> 63) local++;
    if (local) atomicAdd(&cnt, local);
    __syncthreads();
    if (tid == 0) g_V = cnt;

    // gather sorted boxes / confs / areas
    for (int p = tid; p < NN; p += 1024) {
        unsigned long long key = sk[p];
        unsigned int idx = ~(unsigned int)key;
        float4 bb = ((const float4*)bboxes)[idx];
        g_box[p] = bb;
        g_area[p] = (bb.z - bb.x) * (bb.w - bb.y);
        g_conf[p] = ((const float2*)conf)[idx];
    }
}

// ---------------- kernel 3: suppression bitmask tiles ----------------------
__global__ void mask_kernel() {
    int jt = blockIdx.x, it = blockIdx.y;
    if (jt < it) return;
    int V = g_V;
    int nb = (V + 63) >> 6;
    if (it >= nb || jt >= nb) return;

    __shared__ float4 jb[64];
    __shared__ float  ja[64];
    int tid = threadIdx.x;
    int j0 = jt * 64;
    jb[tid] = g_box[j0 + tid];
    ja[tid] = g_area[j0 + tid];
    __syncthreads();

    int i = it * 64 + tid;
    float4 bi = g_box[i];
    float  ai = g_area[i];

    unsigned long long m = 0;
    int jstart = (it == jt) ? (tid + 1) : 0;
    for (int jj = jstart; jj < 64; jj++) {
        float4 bj = jb[jj];
        float iw = fmaxf(fminf(bi.z, bj.z) - fmaxf(bi.x, bj.x), 0.0f);
        float ih = fmaxf(fminf(bi.w, bj.w) - fmaxf(bi.y, bj.y), 0.0f);
        float inter = iw * ih;
        float iou = inter / (ai + ja[jj] - inter + EPSF);
        if (iou > IOU_THR) m |= (1ull << jj);
    }
    g_mask[(size_t)i * NW + jt] = m;
}

// ---------------- kernel 4: sequential greedy reduce (1 block) -------------
__global__ __launch_bounds__(128, 1)
void reduce_kernel() {
    __shared__ unsigned long long keepS[NW];
    __shared__ unsigned long long diag[64];
    __shared__ unsigned long long curw;
    int tid = threadIdx.x;
    int V = g_V;
    int nb = (V + 63) >> 6;

    // init keep: first V bits set
    for (int w = tid; w < NW; w += 128) {
        int base = w * 64;
        unsigned long long k;
        if (base + 64 <= V)      k = ~0ull;
        else if (base >= V)      k = 0ull;
        else                     k = (1ull << (V - base)) - 1ull;
        keepS[w] = k;
    }
    __syncthreads();

    for (int b = 0; b < nb; b++) {
        if (tid < 64)
            diag[tid] = g_mask[(size_t)(b * 64 + tid) * NW + b];
        __syncthreads();

        if (tid == 0) {
            unsigned long long kw = keepS[b];
            #pragma unroll 4
            for (int i = 0; i < 64; i++) {
                if ((kw >> i) & 1ull) kw &= ~diag[i];
            }
            keepS[b] = kw;
            curw = kw;
        }
        __syncthreads();

        unsigned long long kw = curw;
        for (int w = b + 1 + tid; w < nb; w += 128) {
            unsigned long long rem = 0, t = kw;
            while (t) {
                int i = __ffsll(t) - 1;
                t &= t - 1;
                rem |= g_mask[(size_t)(b * 64 + i) * NW + w];
            }
            keepS[w] &= ~rem;
        }
        __syncthreads();
    }

    for (int w = tid; w < NW; w += 128) g_keep[w] = keepS[w];
}

// ---------------- kernel 5: write output -----------------------------------
__global__ void output_kernel(float* __restrict__ out) {
    int p = blockIdx.x * blockDim.x + threadIdx.x;
    if (p >= NN) return;
    float kf = ((g_keep[p >> 6] >> (p & 63)) & 1ull) ? 1.0f : 0.0f;
    float4 bb = g_box[p];
    float2 cc = g_conf[p];
    float2* o = (float2*)(out + (size_t)p * 6);
    o[0] = make_float2(bb.x * SCALER_F * kf, bb.y * SCALER_F * kf);
    o[1] = make_float2(bb.z * SCALER_F * kf, bb.w * SCALER_F * kf);
    o[2] = make_float2(cc.x * kf, cc.y * kf);
}

// ---------------- launch ----------------------------------------------------
extern "C" void kernel_launch(void* const* d_in, const int* in_sizes, int n_in,
                              void* d_out, int out_size) {
    const float* conf  = (const float*)d_in[0];   // (N, 2)
    const float* boxes = (const float*)d_in[1];   // (N, 4)
    if (n_in >= 2 && in_sizes[0] == NN * 4) {     // safety: order by size
        boxes = (const float*)d_in[0];
        conf  = (const float*)d_in[1];
    }
    float* out = (float*)d_out;

    cudaFuncSetAttribute(sort_kernel,
                         cudaFuncAttributeMaxDynamicSharedMemorySize, NN * 8);

    build_keys_kernel<<<NN / 256, 256>>>(conf);
    sort_kernel<<<1, 1024, NN * 8>>>(boxes, conf);
    mask_kernel<<<dim3(NW, NW), 64>>>();
    reduce_kernel<<<1, 128>>>();
    output_kernel<<<NN / 256, 256>>>(out);
}

// round 2
// speedup vs baseline: 1.0175x; 1.0175x over previous
#include <cuda_runtime.h>
#include <cstdint>

#define NN 8192
#define NW 128               // NN/64 words per mask row
#define NBK 4096             // score buckets
#define NCELL 256            // 16x16 spatial grid
#define CS 80.0f             // cell size (>= max box size)
#define THR 0.7f
#define IOU_THR 0.5f
#define EPSF 1e-9f
#define SCALER_F 2.740625f   // 3508/1280

typedef unsigned long long u64;
typedef unsigned int u32;

// ---------------- scratch (device globals; zero-init at load) --------------
__device__ u32 g_inv[NN];
__device__ int g_bucket[NN];
__device__ u32 g_hist[NBK];
__device__ u32 g_bstart[NBK + 1];
__device__ u32 g_bfill[NBK];
__device__ u32 g_kmin, g_kmax;
__device__ int g_V;
__device__ u64 g_skey[NN];
__device__ float4 g_box[NN];
__device__ float2 g_conf[NN];
__device__ float  g_area[NN];
__device__ int g_cellOf[NN];
__device__ u32 g_cellCount[NCELL];
__device__ u32 g_cellStart[NCELL + 1];
__device__ u32 g_cellFill[NCELL];
__device__ int g_cellList[NN];
__device__ u64 g_mask[(size_t)NN * NW];   // rows >= V stay zero forever
__device__ u64 g_keep[NW];

// ---------------- 1: reset small state -------------------------------------
__global__ void init_kernel() {
    int t = blockIdx.x * 256 + threadIdx.x;
    if (t < NBK)   g_hist[t] = 0;
    if (t < NCELL) g_cellCount[t] = 0;
    if (t == 0) { g_kmin = 0xFFFFFFFFu; g_kmax = 0u; g_V = 0; }
}

// ---------------- 2: build keys + min/max + valid count --------------------
__global__ void build_kernel(const float* __restrict__ conf) {
    int i = blockIdx.x * 256 + threadIdx.x;
    float2 c = ((const float2*)conf)[i];
    bool valid = (c.x > THR) || (c.y > THR);
    float s = fmaxf(c.x, c.y);
    // descending score == ascending inv; valid scores are positive floats
    u32 inv = valid ? ~(__float_as_uint(s) | 0x80000000u) : 0xFFFFFFFFu;
    g_inv[i] = inv;
    u32 vb = __ballot_sync(0xFFFFFFFFu, valid);
    u32 mn = valid ? inv : 0xFFFFFFFFu;
    u32 mx = valid ? inv : 0u;
    for (int o = 16; o; o >>= 1) {
        mn = min(mn, __shfl_xor_sync(0xFFFFFFFFu, mn, o));
        mx = max(mx, __shfl_xor_sync(0xFFFFFFFFu, mx, o));
    }
    if ((threadIdx.x & 31) == 0 && vb) {
        atomicMin(&g_kmin, mn);
        atomicMax(&g_kmax, mx);
        atomicAdd(&g_V, __popc(vb));
    }
}

// ---------------- 3: histogram over range-normalized buckets ---------------
__global__ void hist_kernel() {
    int i = blockIdx.x * 256 + threadIdx.x;
    u32 inv = g_inv[i];
    if (inv == 0xFFFFFFFFu) return;
    u32 kmin = g_kmin;
    float scale = (float)(NBK - 1) / (float)max(g_kmax - kmin, 1u);
    u32 b = (u32)((float)(inv - kmin) * scale);   // weakly monotone in inv
    if (b > NBK - 1) b = NBK - 1;
    g_bucket[i] = (int)b;
    atomicAdd(&g_hist[b], 1u);
}

// ---------------- 4: exclusive scan of 4096 bucket counts ------------------
__global__ __launch_bounds__(1024) void scan_kernel() {
    __shared__ u32 ss[1024];
    int tid = threadIdx.x;
    u32 v0 = g_hist[tid * 4], v1 = g_hist[tid * 4 + 1];
    u32 v2 = g_hist[tid * 4 + 2], v3 = g_hist[tid * 4 + 3];
    u32 s = v0 + v1 + v2 + v3;
    ss[tid] = s;
    __syncthreads();
    for (int off = 1; off < 1024; off <<= 1) {
        u32 cur = ss[tid];
        u32 y = (tid >= off) ? ss[tid - off] : 0u;
        __syncthreads();
        ss[tid] = cur + y;
        __syncthreads();
    }
    u32 excl = ss[tid] - s;
    u32 a0 = excl, a1 = excl + v0, a2 = a1 + v1, a3 = a2 + v2;
    g_bstart[tid * 4] = a0;     g_bfill[tid * 4] = a0;
    g_bstart[tid * 4 + 1] = a1; g_bfill[tid * 4 + 1] = a1;
    g_bstart[tid * 4 + 2] = a2; g_bfill[tid * 4 + 2] = a2;
    g_bstart[tid * 4 + 3] = a3; g_bfill[tid * 4 + 3] = a3;
    if (tid == 1023) g_bstart[NBK] = ss[1023];
}

// ---------------- 5: scatter into buckets ----------------------------------
__global__ void scatter_kernel() {
    int i = blockIdx.x * 256 + threadIdx.x;
    u32 inv = g_inv[i];
    if (inv == 0xFFFFFFFFu) return;
    int b = g_bucket[i];
    u32 pos = atomicAdd(&g_bfill[b], 1u);
    g_skey[pos] = ((u64)inv << 32) | (u32)i;
}

// ---------------- 6: per-bucket sort + gather + cell binning ---------------
__global__ void bucket_gather_kernel(const float* __restrict__ boxes,
                                     const float* __restrict__ conf) {
    int b = blockIdx.x * 256 + threadIdx.x;   // 0..4095
    int s = (int)g_bstart[b], e = (int)g_bstart[b + 1];
    // tiny in-place insertion sort: full 64-bit key -> exact stable total order
    for (int a = s + 1; a < e; a++) {
        u64 k = g_skey[a];
        int c = a;
        while (c > s && g_skey[c - 1] > k) { g_skey[c] = g_skey[c - 1]; c--; }
        g_skey[c] = k;
    }
    for (int p = s; p < e; p++) {
        u32 idx = (u32)g_skey[p];
        float4 bb = ((const float4*)boxes)[idx];
        g_box[p] = bb;
        g_area[p] = (bb.z - bb.x) * (bb.w - bb.y);
        g_conf[p] = ((const float2*)conf)[idx];
        int cx = (int)(bb.x * (1.0f / CS)); if (cx > 15) cx = 15;
        int cy = (int)(bb.y * (1.0f / CS)); if (cy > 15) cy = 15;
        int cell = cy * 16 + cx;
        g_cellOf[p] = cell;
        atomicAdd(&g_cellCount[cell], 1u);
    }
}

// ---------------- 7: scan 256 cell counts ----------------------------------
__global__ void cellscan_kernel() {
    __shared__ u32 ss[256];
    int tid = threadIdx.x;
    u32 v = g_cellCount[tid];
    ss[tid] = v;
    __syncthreads();
    for (int off = 1; off < 256; off <<= 1) {
        u32 cur = ss[tid];
        u32 y = (tid >= off) ? ss[tid - off] : 0u;
        __syncthreads();
        ss[tid] = cur + y;
        __syncthreads();
    }
    u32 excl = ss[tid] - v;
    g_cellStart[tid] = excl;
    g_cellFill[tid] = excl;
    if (tid == 255) g_cellStart[NCELL] = ss[255];
}

// ---------------- 8: scatter sorted positions into cells -------------------
__global__ void cellscatter_kernel() {
    int p = blockIdx.x * 256 + threadIdx.x;
    if (p >= g_V) return;
    int c = g_cellOf[p];
    u32 pos = atomicAdd(&g_cellFill[c], 1u);
    g_cellList[pos] = p;
}

// ---------------- 9: sparse suppression mask (spatial hash) ----------------
__global__ void mask_sparse_kernel() {
    int p = blockIdx.x * 128 + threadIdx.x;
    int V = g_V;
    if (p >= V) return;
    int nb = (V + 63) >> 6;
    float4 bp = g_box[p];
    float ap = g_area[p];
    u64* row = &g_mask[(size_t)p * NW];
    for (int w = p >> 6; w < nb; w++) row[w] = 0;   // only words the reducer reads

    const float r = 1.0f / CS;
    int cx0 = (int)fmaxf(floorf((bp.x - 81.0f) * r), 0.0f);
    int cx1 = (int)fminf(floorf(bp.z * r), 15.0f);
    int cy0 = (int)fmaxf(floorf((bp.y - 81.0f) * r), 0.0f);
    int cy1 = (int)fminf(floorf(bp.w * r), 15.0f);

    for (int cy = cy0; cy <= cy1; cy++)
    for (int cx = cx0; cx <= cx1; cx++) {
        int c = cy * 16 + cx;
        int s = (int)g_cellStart[c], e = (int)g_cellStart[c + 1];
        for (int t = s; t < e; t++) {
            int q = g_cellList[t];
            if (q <= p) continue;
            float4 bq = g_box[q];
            float iw = fmaxf(fminf(bp.z, bq.z) - fmaxf(bp.x, bq.x), 0.0f);
            float ih = fmaxf(fminf(bp.w, bq.w) - fmaxf(bp.y, bq.y), 0.0f);
            float inter = iw * ih;
            if (inter > 0.0f) {
                float iou = inter / (ap + g_area[q] - inter + EPSF);
                if (iou > IOU_THR) row[q >> 6] |= (1ull << (q & 63));  // row owned by p
            }
        }
    }
}

// ---------------- 10: sequential greedy reduce (1 block) -------------------
__global__ __launch_bounds__(128, 1)
void reduce_kernel() {
    __shared__ u64 keepS[NW];
    __shared__ u64 diag[64];
    __shared__ u64 curw;
    int tid = threadIdx.x;
    int V = g_V;
    int nb = (V + 63) >> 6;

    for (int w = tid; w < NW; w += 128) {
        int base = w * 64;
        u64 k;
        if (base + 64 <= V)      k = ~0ull;
        else if (base >= V)      k = 0ull;
        else                     k = (1ull << (V - base)) - 1ull;
        keepS[w] = k;
    }
    __syncthreads();

    for (int b = 0; b < nb; b++) {
        if (tid < 64)
            diag[tid] = g_mask[(size_t)(b * 64 + tid) * NW + b];
        __syncthreads();

        if (tid == 0) {
            u64 kw = keepS[b];
            #pragma unroll 4
            for (int i = 0; i < 64; i++) {
                if ((kw >> i) & 1ull) kw &= ~diag[i];
            }
            keepS[b] = kw;
            curw = kw;
        }
        __syncthreads();

        u64 kw = curw;
        for (int w = b + 1 + tid; w < nb; w += 128) {
            u64 rem = 0, t = kw;
            while (t) {
                int i = __ffsll(t) - 1;
                t &= t - 1;
                rem |= g_mask[(size_t)(b * 64 + i) * NW + w];
            }
            keepS[w] &= ~rem;
        }
        __syncthreads();
    }

    for (int w = tid; w < NW; w += 128) g_keep[w] = keepS[w];
}

// ---------------- 11: write output -----------------------------------------
__global__ void output_kernel(float* __restrict__ out) {
    int p = blockIdx.x * 256 + threadIdx.x;
    float2* o = (float2*)(out + (size_t)p * 6);
    if (p < g_V) {
        float kf = ((g_keep[p >> 6] >> (p & 63)) & 1ull) ? 1.0f : 0.0f;
        float4 bb = g_box[p];
        float2 cc = g_conf[p];
        o[0] = make_float2(bb.x * SCALER_F * kf, bb.y * SCALER_F * kf);
        o[1] = make_float2(bb.z * SCALER_F * kf, bb.w * SCALER_F * kf);
        o[2] = make_float2(cc.x * kf, cc.y * kf);
    } else {
        o[0] = make_float2(0.0f, 0.0f);
        o[1] = make_float2(0.0f, 0.0f);
        o[2] = make_float2(0.0f, 0.0f);
    }
}

// ---------------- launch ----------------------------------------------------
extern "C" void kernel_launch(void* const* d_in, const int* in_sizes, int n_in,
                              void* d_out, int out_size) {
    const float* conf  = (const float*)d_in[0];   // (N, 2)
    const float* boxes = (const float*)d_in[1];   // (N, 4)
    if (n_in >= 2 && in_sizes[0] == NN * 4) {     // safety: order by size
        boxes = (const float*)d_in[0];
        conf  = (const float*)d_in[1];
    }
    float* out = (float*)d_out;

    init_kernel<<<16, 256>>>();
    build_kernel<<<32, 256>>>(conf);
    hist_kernel<<<32, 256>>>();
    scan_kernel<<<1, 1024>>>();
    scatter_kernel<<<32, 256>>>();
    bucket_gather_kernel<<<16, 256>>>(boxes, conf);
    cellscan_kernel<<<1, 256>>>();
    cellscatter_kernel<<<32, 256>>>();
    mask_sparse_kernel<<<64, 128>>>();
    reduce_kernel<<<1, 128>>>();
    output_kernel<<<32, 256>>>(out);
}